// round 1
// baseline (speedup 1.0000x reference)
#include <cuda_runtime.h>
#include <mma.h>
#include <cstdint>

using namespace nvcuda;

#define BATCH 256
#define SEQ   512
#define NIN   512
#define NH    128
#define G4    512   // 4*NH
#define NOUT  2

// Scratch (static device globals; no runtime allocation)
__device__ float g_xg[(size_t)SEQ * BATCH * G4];   // 256 MB: x_gates[s][b][col]
__device__ float g_hlast[BATCH * NH];

// ---------------- helpers ----------------
__device__ __forceinline__ float to_tf32(float x) {
    float r; asm("cvt.rna.tf32.f32 %0, %1;" : "=f"(r) : "f"(x)); return r;
}
__device__ __forceinline__ uint64_t ffma2(uint64_t a, uint64_t b, uint64_t c) {
    uint64_t d;
    asm("fma.rn.f32x2 %0, %1, %2, %3;" : "=l"(d) : "l"(a), "l"(b), "l"(c));
    return d;
}
__device__ __forceinline__ uint64_t pack2(float lo, float hi) {
    uint64_t d; asm("mov.b64 %0, {%1, %2};" : "=l"(d) : "f"(lo), "f"(hi)); return d;
}
__device__ __forceinline__ void unpack2(uint64_t v, float& lo, float& hi) {
    asm("mov.b64 {%0, %1}, %2;" : "=f"(lo), "=f"(hi) : "l"(v));
}
__device__ __forceinline__ void cluster_sync_inline() {
    asm volatile("barrier.cluster.arrive.aligned;" ::: "memory");
    asm volatile("barrier.cluster.wait.aligned;" ::: "memory");
}
__device__ __forceinline__ float sigmoid_f(float x) {
    x = fminf(fmaxf(x, -30.f), 30.f);
    return 1.0f / (1.0f + __expf(-x));
}
__device__ __forceinline__ float tanh_f(float x) {
    x = fminf(fmaxf(x, -15.f), 15.f);
    float t = __expf(-2.f * x);
    return __fdividef(1.f - t, 1.f + t);
}

// ================= Phase 1: x_gates[s][b][:] = x[b][s][:] @ Wi (tf32 wmma) =================
#define BM 64
#define BN 64
#define BK 16

__global__ void __launch_bounds__(128) gemm_xw(const float* __restrict__ X,
                                               const float* __restrict__ Wi)
{
    __shared__ float As[BM][BK + 4];   // [m][k], ld=20
    __shared__ float Bs[BK][BN + 4];   // [k][n], ld=68

    const int m0 = blockIdx.x * BM;
    const int n0 = blockIdx.y * BN;
    const int tid = threadIdx.x;
    const int warp = tid >> 5;
    const int wm = warp >> 1, wn = warp & 1;

    wmma::fragment<wmma::accumulator, 16, 16, 8, float> c[2][2];
    #pragma unroll
    for (int i = 0; i < 2; i++)
        #pragma unroll
        for (int j = 0; j < 2; j++)
            wmma::fill_fragment(c[i][j], 0.0f);

    for (int k0 = 0; k0 < NIN; k0 += BK) {
        // Load A tile 64x16 (each thread: 2 float4)
        #pragma unroll
        for (int q = 0; q < 2; q++) {
            int e = tid * 2 + q;                 // 0..255
            int row = e >> 2;                    // 0..63
            int c4 = (e & 3) * 4;                // 0,4,8,12
            const float4 v = *(const float4*)&X[(size_t)(m0 + row) * NIN + k0 + c4];
            As[row][c4 + 0] = to_tf32(v.x);
            As[row][c4 + 1] = to_tf32(v.y);
            As[row][c4 + 2] = to_tf32(v.z);
            As[row][c4 + 3] = to_tf32(v.w);
        }
        // Load B tile 16x64
        #pragma unroll
        for (int q = 0; q < 2; q++) {
            int e = tid * 2 + q;
            int row = e >> 4;                    // 0..15
            int c4 = (e & 15) * 4;               // 0..60
            const float4 v = *(const float4*)&Wi[(size_t)(k0 + row) * G4 + n0 + c4];
            Bs[row][c4 + 0] = to_tf32(v.x);
            Bs[row][c4 + 1] = to_tf32(v.y);
            Bs[row][c4 + 2] = to_tf32(v.z);
            Bs[row][c4 + 3] = to_tf32(v.w);
        }
        __syncthreads();

        #pragma unroll
        for (int kk = 0; kk < BK; kk += 8) {
            wmma::fragment<wmma::matrix_a, 16, 16, 8, wmma::precision::tf32, wmma::row_major> a0, a1;
            wmma::fragment<wmma::matrix_b, 16, 16, 8, wmma::precision::tf32, wmma::row_major> b0, b1;
            wmma::load_matrix_sync(a0, &As[wm * 32][kk], BK + 4);
            wmma::load_matrix_sync(a1, &As[wm * 32 + 16][kk], BK + 4);
            wmma::load_matrix_sync(b0, &Bs[kk][wn * 32], BN + 4);
            wmma::load_matrix_sync(b1, &Bs[kk][wn * 32 + 16], BN + 4);
            wmma::mma_sync(c[0][0], a0, b0, c[0][0]);
            wmma::mma_sync(c[0][1], a0, b1, c[0][1]);
            wmma::mma_sync(c[1][0], a1, b0, c[1][0]);
            wmma::mma_sync(c[1][1], a1, b1, c[1][1]);
        }
        __syncthreads();
    }

    // Epilogue: row m = b*SEQ + s maps to out row s*BATCH + b.
    // A 16-row tile has constant b (SEQ%16==0), consecutive s -> constant stride BATCH*G4.
    #pragma unroll
    for (int i = 0; i < 2; i++) {
        int m = m0 + wm * 32 + i * 16;
        int b = m >> 9;          // m / SEQ
        int s = m & 511;         // m % SEQ
        float* base = g_xg + ((size_t)s * BATCH + b) * G4 + n0 + wn * 32;
        #pragma unroll
        for (int j = 0; j < 2; j++)
            wmma::store_matrix_sync(base + j * 16, c[i][j], BATCH * G4, wmma::mem_row_major);
    }
}

// ================= Phase 2: LSTM recurrence =================
// 64 independent clusters of 2 CTAs; cluster owns 4 batch rows.
// CTA rank r holds Wh columns {g*128 + 64r + [0,64)} for all 4 gates, K=128,
// register-resident as packed f32x2 pairs. h exchanged via DSMEM each step.
__global__ void __launch_bounds__(512, 1) __cluster_dims__(2, 1, 1)
lstm_rec(const float* __restrict__ Wh, const float* __restrict__ bias)
{
    __shared__ __align__(16) float h_s[2][4][NH];   // double-buffered h, replicated per CTA
    __shared__ float gates_s[4][4][64];             // [gate][b][jloc]

    const int tid  = threadIdx.x;
    const int lane = tid & 31;
    const int warp = tid >> 5;
    const int rank  = blockIdx.x & 1;
    const int bbase = (blockIdx.x >> 1) * 4;

    const int gate = warp >> 2;                 // 0..3
    const int sub  = warp & 3;                  // 0..3
    const int jloc = sub * 16 + (lane & 15);    // 0..63
    const int colg = gate * NH + rank * 64 + jloc;  // global gate column
    const int kh   = lane >> 4;                 // k-half: 0 -> [0,64), 1 -> [64,128)

    // Register-resident Wh slice: 32 packed (k,k+1) pairs for this lane's column/half
    uint64_t w[32];
    #pragma unroll
    for (int i = 0; i < 32; i++) {
        int k = kh * 64 + 2 * i;
        float w0 = Wh[(size_t)k * G4 + colg];
        float w1 = Wh[(size_t)(k + 1) * G4 + colg];
        w[i] = pack2(w0, w1);
    }
    const float bias_c = bias[colg];

    // init h = 0
    for (int i = tid; i < 4 * NH; i += 512) (&h_s[0][0][0])[i] = 0.0f;

    float c_reg = 0.0f;                 // cell state owned by update thread (tid<256)
    const int ub = tid >> 6;            // batch 0..3
    const int uj = tid & 63;            // j within this CTA's half

    __syncthreads();
    cluster_sync_inline();              // peer smem initialized before any DSMEM traffic

    int p = 0;
    for (int s = 0; s < SEQ; s++) {
        // Prefetch x-gate contributions (DRAM stream, hidden under the dot products)
        float xg0 = 0.f, xg1 = 0.f, xg2 = 0.f, xg3 = 0.f;
        if (lane < 16) {
            const float* xgp = g_xg + ((size_t)s * BATCH + bbase) * G4 + colg;
            xg0 = xgp[0];
            xg1 = xgp[G4];
            xg2 = xgp[2 * G4];
            xg3 = xgp[3 * G4];
        }

        float v[4];
        #pragma unroll
        for (int b = 0; b < 4; b++) {
            const ulonglong2* h2 = (const ulonglong2*)(&h_s[p][b][kh * 64]);
            uint64_t acc = 0ull;        // packed (0.f, 0.f)
            #pragma unroll
            for (int i = 0; i < 16; i++) {
                ulonglong2 hh = h2[i];
                acc = ffma2(hh.x, w[2 * i], acc);
                acc = ffma2(hh.y, w[2 * i + 1], acc);
            }
            float lo, hi;
            unpack2(acc, lo, hi);
            float t = lo + hi;
            t += __shfl_xor_sync(0xffffffffu, t, 16);   // combine the two k-halves
            v[b] = t;
        }
        if (lane < 16) {
            gates_s[gate][0][jloc] = v[0] + xg0 + bias_c;
            gates_s[gate][1][jloc] = v[1] + xg1 + bias_c;
            gates_s[gate][2][jloc] = v[2] + xg2 + bias_c;
            gates_s[gate][3][jloc] = v[3] + xg3 + bias_c;
        }
        __syncthreads();

        // Elementwise LSTM cell update: threads 0..255 own (b, j) pairs
        if (tid < 256) {
            float gi = gates_s[0][ub][uj];
            float gf = gates_s[1][ub][uj];
            float gg = gates_s[2][ub][uj];
            float go = gates_s[3][ub][uj];
            c_reg = sigmoid_f(gf) * c_reg + sigmoid_f(gi) * tanh_f(gg);
            float hv = sigmoid_f(go) * tanh_f(c_reg);
            int hidx = rank * 64 + uj;
            h_s[p ^ 1][ub][hidx] = hv;                        // local copy
            uint32_t la = (uint32_t)__cvta_generic_to_shared(&h_s[p ^ 1][ub][hidx]);
            uint32_t ra;
            asm("mapa.shared::cluster.u32 %0, %1, %2;" : "=r"(ra) : "r"(la), "r"(rank ^ 1));
            asm volatile("st.shared::cluster.f32 [%0], %1;" :: "r"(ra), "f"(hv) : "memory");
            if (s == SEQ - 1) g_hlast[(bbase + ub) * NH + hidx] = hv;
        }
        cluster_sync_inline();          // release DSMEM stores; also acts as CTA barrier
        p ^= 1;
    }
}

// ================= Phase 3: logits = h_last @ Wd + bd =================
__global__ void final_dense(const float* __restrict__ Wd, const float* __restrict__ bd,
                            float* __restrict__ out)
{
    int b = threadIdx.x;   // 256 threads, 1 block
    float a0 = bd[0], a1 = bd[1];
    const float* hp = g_hlast + b * NH;
    #pragma unroll 8
    for (int k = 0; k < NH; k++) {
        float h = hp[k];
        a0 += h * Wd[k * 2 + 0];
        a1 += h * Wd[k * 2 + 1];
    }
    out[b * 2 + 0] = a0;
    out[b * 2 + 1] = a1;
}

// ================= launch =================
extern "C" void kernel_launch(void* const* d_in, const int* in_sizes, int n_in,
                              void* d_out, int out_size)
{
    const float* x  = (const float*)d_in[0];
    const float* Wi = (const float*)d_in[1];
    const float* Wh = (const float*)d_in[2];
    const float* b  = (const float*)d_in[3];
    const float* Wd = (const float*)d_in[4];
    const float* bd = (const float*)d_in[5];
    float* out = (float*)d_out;

    dim3 g1((BATCH * SEQ) / BM, G4 / BN);   // 2048 x 8
    gemm_xw<<<g1, 128>>>(x, Wi);
    lstm_rec<<<128, 512>>>(Wh, b);          // 64 clusters of 2 CTAs
    final_dense<<<1, 256>>>(Wd, bd, out);
}

// round 2
// speedup vs baseline: 1.1866x; 1.1866x over previous
#include <cuda_runtime.h>
#include <mma.h>
#include <cstdint>

using namespace nvcuda;

#define BATCH 256
#define SEQ   512
#define NIN   512
#define NH    128
#define G4    512   // 4*NH
#define NOUT  2

// Scratch (static device globals; no runtime allocation)
__device__ float g_xg[(size_t)SEQ * BATCH * G4];   // x_gates[s][b][col]
__device__ float g_hlast[BATCH * NH];

// ---------------- helpers ----------------
__device__ __forceinline__ float to_tf32(float x) {
    float r; asm("cvt.rna.tf32.f32 %0, %1;" : "=f"(r) : "f"(x)); return r;
}
__device__ __forceinline__ uint64_t ffma2(uint64_t a, uint64_t b, uint64_t c) {
    uint64_t d;
    asm("fma.rn.f32x2 %0, %1, %2, %3;" : "=l"(d) : "l"(a), "l"(b), "l"(c));
    return d;
}
__device__ __forceinline__ uint64_t pack2(float lo, float hi) {
    uint64_t d; asm("mov.b64 %0, {%1, %2};" : "=l"(d) : "f"(lo), "f"(hi)); return d;
}
__device__ __forceinline__ void unpack2(uint64_t v, float& lo, float& hi) {
    asm("mov.b64 {%0, %1}, %2;" : "=f"(lo), "=f"(hi) : "l"(v));
}
__device__ __forceinline__ void cluster_sync_inline() {
    asm volatile("barrier.cluster.arrive.aligned;" ::: "memory");
    asm volatile("barrier.cluster.wait.aligned;" ::: "memory");
}
__device__ __forceinline__ float sigmoid_f(float x) {
    x = fminf(fmaxf(x, -30.f), 30.f);
    return 1.0f / (1.0f + __expf(-x));
}
__device__ __forceinline__ float tanh_f(float x) {
    x = fminf(fmaxf(x, -15.f), 15.f);
    float t = __expf(-2.f * x);
    return __fdividef(1.f - t, 1.f + t);
}
__device__ __forceinline__ void cp_async16(void* smem, const void* g) {
    uint32_t s = (uint32_t)__cvta_generic_to_shared(smem);
    asm volatile("cp.async.cg.shared.global [%0], [%1], 16;" :: "r"(s), "l"(g));
}
__device__ __forceinline__ void mbar_init(uint32_t addr, uint32_t cnt) {
    asm volatile("mbarrier.init.shared.b64 [%0], %1;" :: "r"(addr), "r"(cnt) : "memory");
}
__device__ __forceinline__ void mbar_arrive_remote(uint32_t raddr) {
    asm volatile("mbarrier.arrive.release.cluster.shared::cluster.b64 _, [%0];"
                 :: "r"(raddr) : "memory");
}
__device__ __forceinline__ void mbar_wait_cluster(uint32_t addr, uint32_t parity) {
    uint32_t done;
    asm volatile(
        "{\n .reg .pred p;\n"
        " mbarrier.try_wait.parity.acquire.cluster.shared::cta.b64 p, [%1], %2;\n"
        " selp.b32 %0, 1, 0, p;\n}"
        : "=r"(done) : "r"(addr), "r"(parity) : "memory");
    while (!done) {
        asm volatile(
            "{\n .reg .pred p;\n"
            " mbarrier.try_wait.parity.acquire.cluster.shared::cta.b64 p, [%1], %2, 0x989680;\n"
            " selp.b32 %0, 1, 0, p;\n}"
            : "=r"(done) : "r"(addr), "r"(parity) : "memory");
    }
}

// ================= Phase 1: x_gates = x @ Wi (tf32 wmma, cp.async pipelined) =================
#define BM 128
#define BN 128
#define BK 16
#define PADA 8
#define PADB 8
#define LDA (BK + PADA)   // 24
#define LDB (BN + PADB)   // 136

__global__ void __launch_bounds__(256) gemm_xw(const float* __restrict__ X,
                                               const float* __restrict__ Wi)
{
    __shared__ float As[2][BM][LDA];
    __shared__ float Bs[2][BK][LDB];

    const int m0 = blockIdx.x * BM;
    const int n0 = blockIdx.y * BN;
    const int tid = threadIdx.x;
    const int warp = tid >> 5;
    const int wm = warp >> 2;     // 0..1 : 64-row slab
    const int wn = warp & 3;      // 0..3 : 32-col slab

    wmma::fragment<wmma::accumulator, 16, 16, 8, float> c[4][2];
    #pragma unroll
    for (int i = 0; i < 4; i++)
        #pragma unroll
        for (int j = 0; j < 2; j++)
            wmma::fill_fragment(c[i][j], 0.0f);

    auto load_tiles = [&](int kt, int buf) {
        const int k0 = kt * BK;
        #pragma unroll
        for (int q = 0; q < 2; q++) {
            int e = tid + q * 256;
            int row = e >> 2;            // 0..127
            int c4 = (e & 3) * 4;        // 0..12
            cp_async16(&As[buf][row][c4], &X[(size_t)(m0 + row) * NIN + k0 + c4]);
        }
        #pragma unroll
        for (int q = 0; q < 2; q++) {
            int e = tid + q * 256;
            int row = e >> 5;            // 0..15
            int c4 = (e & 31) * 4;       // 0..124
            cp_async16(&Bs[buf][row][c4], &Wi[(size_t)(k0 + row) * G4 + n0 + c4]);
        }
        asm volatile("cp.async.commit_group;" ::: "memory");
    };

    load_tiles(0, 0);

    const int NT = NIN / BK;   // 32
    for (int kt = 0; kt < NT; kt++) {
        if (kt + 1 < NT) {
            load_tiles(kt + 1, (kt + 1) & 1);
            asm volatile("cp.async.wait_group 1;" ::: "memory");
        } else {
            asm volatile("cp.async.wait_group 0;" ::: "memory");
        }
        __syncthreads();

        const int buf = kt & 1;
        #pragma unroll
        for (int kk = 0; kk < BK; kk += 8) {
            wmma::fragment<wmma::matrix_a, 16, 16, 8, wmma::precision::tf32, wmma::row_major> af[4];
            wmma::fragment<wmma::matrix_b, 16, 16, 8, wmma::precision::tf32, wmma::row_major> bf[2];
            #pragma unroll
            for (int i = 0; i < 4; i++) {
                wmma::load_matrix_sync(af[i], &As[buf][wm * 64 + i * 16][kk], LDA);
                #pragma unroll
                for (int t = 0; t < af[i].num_elements; t++) af[i].x[t] = to_tf32(af[i].x[t]);
            }
            #pragma unroll
            for (int j = 0; j < 2; j++) {
                wmma::load_matrix_sync(bf[j], &Bs[buf][kk][wn * 32 + j * 16], LDB);
                #pragma unroll
                for (int t = 0; t < bf[j].num_elements; t++) bf[j].x[t] = to_tf32(bf[j].x[t]);
            }
            #pragma unroll
            for (int i = 0; i < 4; i++)
                #pragma unroll
                for (int j = 0; j < 2; j++)
                    wmma::mma_sync(c[i][j], af[i], bf[j], c[i][j]);
        }
        __syncthreads();
    }

    // Epilogue: gmem row m = b*SEQ + s -> g_xg row s*BATCH + b. 128-row tile: constant b.
    #pragma unroll
    for (int i = 0; i < 4; i++) {
        int m = m0 + wm * 64 + i * 16;
        int b = m >> 9;
        int s = m & 511;
        float* base = g_xg + ((size_t)s * BATCH + b) * G4 + n0 + wn * 32;
        #pragma unroll
        for (int j = 0; j < 2; j++)
            wmma::store_matrix_sync(base + j * 16, c[i][j], (size_t)BATCH * G4, wmma::mem_row_major);
    }
}

// ================= Phase 2: LSTM recurrence =================
// 64 clusters x 2 CTAs. Warps 0-7: k-half 0 ([0,64)); warps 8-15: k-half 1.
// Each warp owns 32 gate-columns of one gate (for this CTA's rank-half of j).
// Cross-CTA h exchange: DSMEM stores + 1-arrival mbarrier handshake (no barrier.cluster in loop).
// Warps whose k-half was produced locally (kh == rank) start dots BEFORE the peer wait.
__global__ void __launch_bounds__(512, 1) __cluster_dims__(2, 1, 1)
lstm_rec(const float* __restrict__ Wh, const float* __restrict__ bias)
{
    __shared__ __align__(16) float h_s[2][4][NH];     // double-buffered h
    __shared__ float part[2][4][4][64];               // [kh][gate][b][jloc]
    __shared__ __align__(8) unsigned long long mbar;

    const int tid  = threadIdx.x;
    const int lane = tid & 31;
    const int warp = tid >> 5;
    const int rank  = blockIdx.x & 1;
    const int bbase = (blockIdx.x >> 1) * 4;

    const int kh   = warp >> 3;                 // k in [kh*64, kh*64+64)
    const int w7   = warp & 7;
    const int gate = w7 >> 1;                   // 0..3
    const int jloc = (w7 & 1) * 32 + lane;      // 0..63
    const int colg = gate * NH + rank * 64 + jloc;

    // Register-resident Wh half-column: 32 packed (k,k+1) pairs
    uint64_t w[32];
    #pragma unroll
    for (int i = 0; i < 32; i++) {
        int k = kh * 64 + 2 * i;
        w[i] = pack2(Wh[(size_t)k * G4 + colg], Wh[(size_t)(k + 1) * G4 + colg]);
    }

    // Update-thread constants (tid < 256): (b, j) ownership
    const int ub = tid >> 6;
    const int uj = tid & 63;
    const int hidx = rank * 64 + uj;
    float bi = 0.f, bfo = 0.f, bg = 0.f, bo = 0.f;
    if (tid < 256) {
        bi  = bias[0 * NH + hidx];
        bfo = bias[1 * NH + hidx];
        bg  = bias[2 * NH + hidx];
        bo  = bias[3 * NH + hidx];
    }
    float c_reg = 0.0f;

    // mbarrier + remote addresses
    const uint32_t mloc = (uint32_t)__cvta_generic_to_shared(&mbar);
    uint32_t mrem;
    asm("mapa.shared::cluster.u32 %0, %1, %2;" : "=r"(mrem) : "r"(mloc), "r"(rank ^ 1));
    uint32_t hrem[2];
    #pragma unroll
    for (int pp = 0; pp < 2; pp++) {
        uint32_t la = (uint32_t)__cvta_generic_to_shared(&h_s[pp][ub][hidx]);
        asm("mapa.shared::cluster.u32 %0, %1, %2;" : "=r"(hrem[pp]) : "r"(la), "r"(rank ^ 1));
    }

    if (tid == 0) mbar_init(mloc, 1);
    for (int i = tid; i < 4 * NH; i += 512) (&h_s[0][0][0])[i] = 0.0f;
    __syncthreads();
    cluster_sync_inline();              // peer mbar init'd + h zeroed before any traffic
    if (tid == 0) mbar_arrive_remote(mrem);   // completes phase 0 (peer's "step -1 output ready")

    int p = 0;
    for (int s = 0; s < SEQ; s++) {
        // xg prefetch (DRAM, consumed at update — long latency fully hidden)
        float xgi = 0.f, xgf = 0.f, xgg = 0.f, xgo = 0.f;
        if (tid < 256) {
            const float* xp = g_xg + ((size_t)s * BATCH + bbase + ub) * G4 + hidx;
            xgi = xp[0];
            xgf = xp[NH];
            xgg = xp[2 * NH];
            xgo = xp[3 * NH];
        }

        // Dot products. Local-half warps (kh == rank) need no peer data: start immediately.
        #define DO_DOT()                                                          \
        do {                                                                      \
            _Pragma("unroll")                                                     \
            for (int b = 0; b < 4; b++) {                                         \
                const ulonglong2* h2 = (const ulonglong2*)&h_s[p][b][kh * 64];    \
                uint64_t a0 = 0ull, a1 = 0ull;                                    \
                _Pragma("unroll")                                                 \
                for (int i = 0; i < 8; i++) {                                     \
                    ulonglong2 ha = h2[2 * i];                                    \
                    ulonglong2 hb = h2[2 * i + 1];                                \
                    a0 = ffma2(ha.x, w[4 * i + 0], a0);                           \
                    a0 = ffma2(ha.y, w[4 * i + 1], a0);                           \
                    a1 = ffma2(hb.x, w[4 * i + 2], a1);                           \
                    a1 = ffma2(hb.y, w[4 * i + 3], a1);                           \
                }                                                                 \
                float l0, h0, l1, h1;                                             \
                unpack2(a0, l0, h0);                                              \
                unpack2(a1, l1, h1);                                              \
                part[kh][gate][b][jloc] = (l0 + h0) + (l1 + h1);                  \
            }                                                                     \
        } while (0)

        if (kh == rank) DO_DOT();
        mbar_wait_cluster(mloc, s & 1);          // peer's step s-1 h is visible
        if (kh != rank) DO_DOT();
        __syncthreads();                          // partials visible

        if (tid < 256) {
            float gi = part[0][0][ub][uj] + part[1][0][ub][uj] + xgi + bi;
            float gf = part[0][1][ub][uj] + part[1][1][ub][uj] + xgf + bfo;
            float gg = part[0][2][ub][uj] + part[1][2][ub][uj] + xgg + bg;
            float go = part[0][3][ub][uj] + part[1][3][ub][uj] + xgo + bo;
            c_reg = sigmoid_f(gf) * c_reg + sigmoid_f(gi) * tanh_f(gg);
            float hv = sigmoid_f(go) * tanh_f(c_reg);
            h_s[p ^ 1][ub][hidx] = hv;
            asm volatile("st.shared::cluster.f32 [%0], %1;" :: "r"(hrem[p ^ 1]), "f"(hv) : "memory");
            if (s == SEQ - 1) g_hlast[(bbase + ub) * NH + hidx] = hv;
        }
        __syncthreads();                          // local h + DSMEM stores ordered before arrive
        if (tid == 0) mbar_arrive_remote(mrem);   // completes peer's phase s+1
        p ^= 1;
    }
    cluster_sync_inline();   // keep both CTAs alive for in-flight DSMEM/arrive traffic
}

// ================= Phase 3: logits = h_last @ Wd + bd =================
__global__ void final_dense(const float* __restrict__ Wd, const float* __restrict__ bd,
                            float* __restrict__ out)
{
    int b = threadIdx.x;   // 256 threads, 1 block
    float a0 = bd[0], a1 = bd[1];
    const float* hp = g_hlast + b * NH;
    #pragma unroll 8
    for (int k = 0; k < NH; k++) {
        float h = hp[k];
        a0 += h * Wd[k * 2 + 0];
        a1 += h * Wd[k * 2 + 1];
    }
    out[b * 2 + 0] = a0;
    out[b * 2 + 1] = a1;
}

// ================= launch =================
extern "C" void kernel_launch(void* const* d_in, const int* in_sizes, int n_in,
                              void* d_out, int out_size)
{
    const float* x  = (const float*)d_in[0];
    const float* Wi = (const float*)d_in[1];
    const float* Wh = (const float*)d_in[2];
    const float* b  = (const float*)d_in[3];
    const float* Wd = (const float*)d_in[4];
    const float* bd = (const float*)d_in[5];
    float* out = (float*)d_out;

    dim3 g1((BATCH * SEQ) / BM, G4 / BN);   // 1024 x 4
    gemm_xw<<<g1, 256>>>(x, Wi);
    lstm_rec<<<128, 512>>>(Wh, b);          // 64 clusters of 2 CTAs
    final_dense<<<1, 256>>>(Wd, bd, out);
}